// round 2
// baseline (speedup 1.0000x reference)
#include <cuda_runtime.h>
#include <math.h>

#define CB 4
#define CL 2048
#define CC 1024
#define CNH 16
#define CHD 64
#define CK 16
#define CF4 256
#define CNC 128

// ---------------- scratch (device globals; no allocations allowed) ----------
__device__ float g_Q [CB*CL*CC];
__device__ float g_K [CB*CL*CC];
__device__ float g_V [CB*CL*CC];
__device__ float g_Y [CB*CL*CC];
__device__ float g_LR[CB*CNH*CL];

// ---------------- math helpers ----------------------------------------------
__device__ __forceinline__ float gelu_f(float x){
  float x2 = x*x;
  float t = tanhf(0.79788456f*x*(1.0f+0.044715f*x2));
  return 0.5f*x*(1.0f+t);
}
__device__ __forceinline__ float gelu_bwd_f(float x){
  float x2 = x*x;
  float t = tanhf(0.79788456f*x*(1.0f+0.044715f*x2));
  return 0.5f*x*((1.0f-t*t)*(0.79788456f + 0.1070322243f*x2)) + 0.5f*(1.0f+t);
}

// ---------------- GEMM: C[M,N] = A[M,K] * B[N,K]^T  (fp32, 64x64 tile) ------
__global__ __launch_bounds__(256) void gemm_nt64(
    const float* __restrict__ A, const float* __restrict__ B,
    float* __restrict__ C, int M, int N, int Kd)
{
  __shared__ float As[16][64];
  __shared__ float Bs[16][64];
  int nt = N >> 6;
  int by = blockIdx.x / nt;
  int bx = blockIdx.x % nt;
  int tid = threadIdx.x;
  int lrow = tid >> 2;
  int lcol = (tid & 3) << 2;
  const float* Ap = A + (size_t)(by*64 + lrow)*Kd + lcol;
  const float* Bp = B + (size_t)(bx*64 + lrow)*Kd + lcol;
  int ty = tid >> 4, tx = tid & 15;
  float acc[4][4];
  #pragma unroll
  for (int i=0;i<4;i++){
    #pragma unroll
    for (int j=0;j<4;j++) acc[i][j]=0.f;
  }
  for (int k0=0; k0<Kd; k0+=16) {
    float4 a4 = *(const float4*)(Ap + k0);
    float4 b4 = *(const float4*)(Bp + k0);
    __syncthreads();
    As[lcol+0][lrow]=a4.x; As[lcol+1][lrow]=a4.y; As[lcol+2][lrow]=a4.z; As[lcol+3][lrow]=a4.w;
    Bs[lcol+0][lrow]=b4.x; Bs[lcol+1][lrow]=b4.y; Bs[lcol+2][lrow]=b4.z; Bs[lcol+3][lrow]=b4.w;
    __syncthreads();
    #pragma unroll
    for (int k=0;k<16;k++){
      float4 av = *(const float4*)&As[k][ty*4];
      float4 bv = *(const float4*)&Bs[k][tx*4];
      acc[0][0]+=av.x*bv.x; acc[0][1]+=av.x*bv.y; acc[0][2]+=av.x*bv.z; acc[0][3]+=av.x*bv.w;
      acc[1][0]+=av.y*bv.x; acc[1][1]+=av.y*bv.y; acc[1][2]+=av.y*bv.z; acc[1][3]+=av.y*bv.w;
      acc[2][0]+=av.z*bv.x; acc[2][1]+=av.z*bv.y; acc[2][2]+=av.z*bv.z; acc[2][3]+=av.z*bv.w;
      acc[3][0]+=av.w*bv.x; acc[3][1]+=av.w*bv.y; acc[3][2]+=av.w*bv.z; acc[3][3]+=av.w*bv.w;
    }
  }
  #pragma unroll
  for (int i=0;i<4;i++){
    float4 o = make_float4(acc[i][0],acc[i][1],acc[i][2],acc[i][3]);
    *(float4*)&C[(size_t)(by*64+ty*4+i)*N + bx*64 + tx*4] = o;
  }
}

// ---------------- RoPE (interleaved pairs, pos = l mod 16) ------------------
__global__ __launch_bounds__(256) void rope_kernel(float* __restrict__ Q, float* __restrict__ Kt)
{
  const int PAIRS = CB*CL*CNH*(CHD/2); // 4194304
  int i = blockIdx.x*blockDim.x + threadIdx.x;
  if (i >= 2*PAIRS) return;
  float* T = (i < PAIRS) ? Q : Kt;
  int j = (i < PAIRS) ? i : (i - PAIRS);
  int p = j & 31; j >>= 5;
  int h = j & 15; j >>= 4;
  int l = j & 2047;
  int b = j >> 11;
  float pos = (float)(l & 15);
  // inv_freq = 10000^(-p/32) = exp2(-p/32 * log2(10000))
  float ang = pos * exp2f(-(float)p * (13.287712379549449f/32.0f));
  float sn, cs;
  sincosf(ang, &sn, &cs);
  size_t base = ((size_t)(b*CL + l))*CC + h*CHD + 2*p;
  float2 x = *(float2*)&T[base];
  float2 y;
  y.x = x.x*cs - x.y*sn;
  y.y = x.y*cs + x.x*sn;
  *(float2*)&T[base] = y;
}

// ---------------- ttt_lr sigmoid dots: lr[b,h,l] ----------------------------
__global__ __launch_bounds__(256) void lr_kernel(
    const float* __restrict__ hs, const float* __restrict__ w,
    const float* __restrict__ bias, float* __restrict__ lr)
{
  __shared__ float row[CC];
  int bl = blockIdx.x;            // b*L + l
  int tid = threadIdx.x;
  ((float4*)row)[tid] = ((const float4*)(hs + (size_t)bl*CC))[tid];
  __syncthreads();
  int h = tid >> 4, ln = tid & 15;
  float acc = 0.f;
  for (int c0 = ln*4; c0 < CC; c0 += 64){
    float4 r = *(const float4*)&row[c0];
    float4 wv = *(const float4*)&w[h*CC + c0];
    acc += r.x*wv.x + r.y*wv.y + r.z*wv.z + r.w*wv.w;
  }
  #pragma unroll
  for (int o=8;o;o>>=1) acc += __shfl_xor_sync(0xffffffffu, acc, o);
  if (ln == 0){
    int b = bl >> 11, l = bl & 2047;
    float v = acc + bias[h];
    lr[((size_t)(b*CNH + h))*CL + l] = 1.0f/(1.0f + expf(-v));
  }
}

// ---------------- scan kernel: one CTA per (b,h), all state in smem ---------
// smem float offsets:
#define OW1 0        /* [64][256]           */
#define OW2 16384    /* [256][65]           */
#define OB1 33024    /* [256]               */
#define OB2 33280    /* [64]                */
#define OLW 33344    /* [64] ln weight      */
#define OLB 33408    /* [64] ln bias        */
#define OXQ 33472    /* [16][68]            */
#define OXK 34560
#define OXV 35648
#define OZ2 36736    /* [16][68] Z2/Z2bar   */
#define OG2 37824    /* [16][68] gZ2        */
#define OCC 38912    /* [16][17] coeffs     */
#define OTK 39184    /* [16] token_idx      */
#define OLR 39200    /* [16] lr vec         */
#define OZ1 39216    /* [16][260] Z1/X2bar  */
#define OX2 43376    /* [16][260] X2        */
#define OG1 47536    /* [16][260] gZ1       */
#define SCAN_FLOATS 51696
#define SCAN_SMEM (SCAN_FLOATS*4)

__global__ __launch_bounds__(256) void scan_kernel(
  const float* __restrict__ Q, const float* __restrict__ Kx, const float* __restrict__ V,
  const float* __restrict__ LR, const float* __restrict__ lti,
  const float* __restrict__ lnw, const float* __restrict__ lnb,
  const float* __restrict__ W1g, const float* __restrict__ b1g,
  const float* __restrict__ W2g, const float* __restrict__ b2g,
  float* __restrict__ Y)
{
  extern __shared__ float sm[];
  const int t = threadIdx.x;
  const int bh = blockIdx.x;
  const int b = bh >> 4, h = bh & 15;
  float* sW1 = sm + OW1;
  float* sW2 = sm + OW2;
  float* sb1 = sm + OB1;
  float* sb2 = sm + OB2;
  float* sLW = sm + OLW;
  float* sLB = sm + OLB;
  float* sXQ = sm + OXQ;
  float* sXK = sm + OXK;
  float* sXV = sm + OXV;
  float* sZ2 = sm + OZ2;
  float* sG2 = sm + OG2;
  float* sC  = sm + OCC;
  float* sTok= sm + OTK;
  float* sLr = sm + OLR;
  float* sZ1 = sm + OZ1;
  float* sX2 = sm + OX2;
  float* sG1 = sm + OG1;

  // init state
  for (int idx = t; idx < 16384; idx += 256) sW1[idx] = W1g[h*16384 + idx];
  for (int idx = t; idx < 16384; idx += 256) {
    int f = idx >> 6, d = idx & 63;
    sW2[f*65+d] = W2g[h*16384 + idx];
  }
  sb1[t] = b1g[h*256+t];
  if (t < 64) { sb2[t] = b2g[h*64+t]; sLW[t] = lnw[h*64+t]; sLB[t] = lnb[h*64+t]; }
  if (t < 16) sTok[t] = fmaxf(1.0f/(float)(t+1) + lti[t], 0.0f);
  __syncthreads();

  const int i16 = t >> 4, l16 = t & 15;   // (row, lane) mapping for 16-row ops
  const int d64 = t & 63, q4 = t >> 6;    // (col, row-group) mapping for HD ops

  for (int n = 0; n < CNC; n++) {
    const int l0 = n*16;
    // ---- load tiles
    {
      size_t gbase = ((size_t)(b*CL + l0 + i16))*CC + h*CHD + l16*4;
      int sbase = i16*68 + l16*4;
      *(float4*)&sXQ[sbase] = *(const float4*)&Q [gbase];
      *(float4*)&sXK[sbase] = *(const float4*)&Kx[gbase];
      *(float4*)&sXV[sbase] = *(const float4*)&V [gbase];
    }
    if (t < 16) sLr[t] = LR[((size_t)bh)*CL + l0 + t] * (1.0f/64.0f);
    __syncthreads();

    // ---- Z1 = XK@W1 + b1 ; X2 = gelu(Z1)   (thread t owns column t)
    {
      float acc[16];
      #pragma unroll
      for (int i=0;i<16;i++) acc[i] = sb1[t];
      #pragma unroll 4
      for (int d0=0; d0<64; d0+=4) {
        float w0 = sW1[(d0+0)*256+t], w1 = sW1[(d0+1)*256+t];
        float w2 = sW1[(d0+2)*256+t], w3 = sW1[(d0+3)*256+t];
        #pragma unroll
        for (int i=0;i<16;i++) {
          float4 xk = *(const float4*)&sXK[i*68+d0];
          acc[i] += xk.x*w0 + xk.y*w1 + xk.z*w2 + xk.w*w3;
        }
      }
      #pragma unroll
      for (int i=0;i<16;i++){ float z = acc[i]; sZ1[i*260+t] = z; sX2[i*260+t] = gelu_f(z); }
    }
    __syncthreads();

    // ---- Z2 = X2@W2 + b2   (thread: col d64, rows q4*4+r)
    {
      float a2[4];
      #pragma unroll
      for (int r=0;r<4;r++) a2[r] = sb2[d64];
      #pragma unroll 4
      for (int f0=0; f0<256; f0+=4) {
        float w0 = sW2[(f0+0)*65+d64], w1 = sW2[(f0+1)*65+d64];
        float w2 = sW2[(f0+2)*65+d64], w3 = sW2[(f0+3)*65+d64];
        #pragma unroll
        for (int r=0;r<4;r++) {
          float4 x = *(const float4*)&sX2[(q4*4+r)*260+f0];
          a2[r] += x.x*w0 + x.y*w1 + x.z*w2 + x.w*w3;
        }
      }
      #pragma unroll
      for (int r=0;r<4;r++) sZ2[(q4*4+r)*68+d64] = a2[r];
    }
    // ---- Attn1 coefficients c[i,j] = tok[i]*lrv[j]*(xq_i.xk_j + 1), j<=i
    {
      float c = 0.0f;
      if (l16 <= i16) {
        float a = 0.0f;
        #pragma unroll
        for (int d0=0; d0<64; d0+=4) {
          float4 xq = *(const float4*)&sXQ[i16*68+d0];
          float4 xk = *(const float4*)&sXK[l16*68+d0];
          a += xq.x*xk.x + xq.y*xk.y + xq.z*xk.z + xq.w*xk.w;
        }
        c = sTok[i16]*sLr[l16]*(a + 1.0f);
      }
      sC[i16*17+l16] = c;
    }
    __syncthreads();

    // ---- gZ2 = ln_fused_l2_bwd(Z2, XV-XK)
    {
      int base = i16*68 + l16*4;
      float4 x = *(const float4*)&sZ2[base];
      float s  = x.x+x.y+x.z+x.w;
      float ss = x.x*x.x + x.y*x.y + x.z*x.z + x.w*x.w;
      #pragma unroll
      for (int o=8;o;o>>=1){ s += __shfl_xor_sync(0xffffffffu, s, o); ss += __shfl_xor_sync(0xffffffffu, ss, o); }
      float mu = s*(1.0f/64.0f);
      float var = ss*(1.0f/64.0f) - mu*mu;
      float rstd = rsqrtf(var + 1e-6f);
      float4 xh;
      xh.x=(x.x-mu)*rstd; xh.y=(x.y-mu)*rstd; xh.z=(x.z-mu)*rstd; xh.w=(x.w-mu)*rstd;
      float4 g  = *(const float4*)&sLW[l16*4];
      float4 bb = *(const float4*)&sLB[l16*4];
      float4 xv = *(const float4*)&sXV[base];
      float4 xk = *(const float4*)&sXK[base];
      float4 go;
      go.x = (g.x*xh.x + bb.x - (xv.x - xk.x))*g.x;
      go.y = (g.y*xh.y + bb.y - (xv.y - xk.y))*g.y;
      go.z = (g.z*xh.z + bb.z - (xv.z - xk.z))*g.z;
      go.w = (g.w*xh.w + bb.w - (xv.w - xk.w))*g.w;
      float sg  = go.x+go.y+go.z+go.w;
      float sgx = go.x*xh.x + go.y*xh.y + go.z*xh.z + go.w*xh.w;
      #pragma unroll
      for (int o=8;o;o>>=1){ sg += __shfl_xor_sync(0xffffffffu, sg, o); sgx += __shfl_xor_sync(0xffffffffu, sgx, o); }
      float k1 = rstd*(1.0f/64.0f);
      float4 o4;
      o4.x = (64.0f*go.x - sg - xh.x*sgx)*k1;
      o4.y = (64.0f*go.y - sg - xh.y*sgx)*k1;
      o4.z = (64.0f*go.z - sg - xh.z*sgx)*k1;
      o4.w = (64.0f*go.w - sg - xh.w*sgx)*k1;
      *(float4*)&sG2[base] = o4;
    }
    __syncthreads();

    // ---- gZ1 = (gZ2 @ W2^T) * gelu_bwd(Z1)   (column t)
    {
      float acc[16];
      #pragma unroll
      for (int i=0;i<16;i++) acc[i]=0.f;
      #pragma unroll 4
      for (int d0=0; d0<64; d0+=4) {
        float w0 = sW2[t*65+d0+0], w1 = sW2[t*65+d0+1];
        float w2 = sW2[t*65+d0+2], w3 = sW2[t*65+d0+3];
        #pragma unroll
        for (int i=0;i<16;i++) {
          float4 gz = *(const float4*)&sG2[i*68+d0];
          acc[i] += gz.x*w0 + gz.y*w1 + gz.z*w2 + gz.w*w3;
        }
      }
      #pragma unroll
      for (int i=0;i<16;i++) sG1[i*260+t] = acc[i]*gelu_bwd_f(sZ1[i*260+t]);
    }
    // (no sync: sG1 column t and sZ1 column t are private to this thread below)

    // ---- Z1_bar -> X2_bar = gelu(Z1_bar)  (column t, overwrite sZ1)
    {
      float acc[16];
      #pragma unroll
      for (int i=0;i<16;i++) acc[i] = sb1[t];
      #pragma unroll 4
      for (int d0=0; d0<64; d0+=4) {
        float w0 = sW1[(d0+0)*256+t], w1 = sW1[(d0+1)*256+t];
        float w2 = sW1[(d0+2)*256+t], w3 = sW1[(d0+3)*256+t];
        #pragma unroll
        for (int i=0;i<16;i++) {
          float4 xq = *(const float4*)&sXQ[i*68+d0];
          acc[i] += xq.x*w0 + xq.y*w1 + xq.z*w2 + xq.w*w3;
        }
      }
      float gz[16];
      #pragma unroll
      for (int j=0;j<16;j++) gz[j] = sG1[j*260+t];
      #pragma unroll
      for (int i=0;i<16;i++){
        float a = acc[i];
        #pragma unroll
        for (int j=0;j<=i;j++) a -= sC[i*17+j]*gz[j];
        sZ1[i*260+t] = gelu_f(a);
      }
    }
    __syncthreads();

    // ---- Attn2 coefficients c2[i,j] = tok[i]*lrv[j]*(x2bar_i . x2_j + 1), j<=i
    {
      float c = 0.0f;
      if (l16 <= i16) {
        float a = 0.0f;
        #pragma unroll 8
        for (int f0=0; f0<256; f0+=4) {
          float4 xb = *(const float4*)&sZ1[i16*260+f0];
          float4 x2 = *(const float4*)&sX2[l16*260+f0];
          a += xb.x*x2.x + xb.y*x2.y + xb.z*x2.z + xb.w*x2.w;
        }
        c = sTok[i16]*sLr[l16]*(a + 1.0f);
      }
      sC[i16*17+l16] = c;
    }
    __syncthreads();

    // ---- Z2_bar = X2bar@W2 + b2 - corrections  (col d64, rows q4*4+r) -> sZ2
    {
      float a2[4];
      #pragma unroll
      for (int r=0;r<4;r++) a2[r] = sb2[d64];
      #pragma unroll 4
      for (int f0=0; f0<256; f0+=4) {
        float w0 = sW2[(f0+0)*65+d64], w1 = sW2[(f0+1)*65+d64];
        float w2 = sW2[(f0+2)*65+d64], w3 = sW2[(f0+3)*65+d64];
        #pragma unroll
        for (int r=0;r<4;r++) {
          float4 x = *(const float4*)&sZ1[(q4*4+r)*260+f0];
          a2[r] += x.x*w0 + x.y*w1 + x.z*w2 + x.w*w3;
        }
      }
      float gz[16];
      #pragma unroll
      for (int j=0;j<16;j++) gz[j] = sG2[j*68+d64];
      #pragma unroll
      for (int r=0;r<4;r++){
        int i = q4*4+r;
        float a = a2[r];
        for (int j=0;j<=i;j++) a -= sC[i*17+j]*gz[j];
        sZ2[i*68+d64] = a;
      }
    }
    __syncthreads();

    // ---- output: Y = XQ + ln_fwd(Z2_bar)
    {
      int base = i16*68 + l16*4;
      float4 x = *(const float4*)&sZ2[base];
      float s  = x.x+x.y+x.z+x.w;
      float ss = x.x*x.x + x.y*x.y + x.z*x.z + x.w*x.w;
      #pragma unroll
      for (int o=8;o;o>>=1){ s += __shfl_xor_sync(0xffffffffu, s, o); ss += __shfl_xor_sync(0xffffffffu, ss, o); }
      float mu = s*(1.0f/64.0f);
      float var = ss*(1.0f/64.0f) - mu*mu;
      float rstd = rsqrtf(var + 1e-6f);
      float4 g  = *(const float4*)&sLW[l16*4];
      float4 bb = *(const float4*)&sLB[l16*4];
      float4 xq = *(const float4*)&sXQ[base];
      float4 o4;
      o4.x = g.x*(x.x-mu)*rstd + bb.x + xq.x;
      o4.y = g.y*(x.y-mu)*rstd + bb.y + xq.y;
      o4.z = g.z*(x.z-mu)*rstd + bb.z + xq.z;
      o4.w = g.w*(x.w-mu)*rstd + bb.w + xq.w;
      size_t gbase = ((size_t)(b*CL + l0 + i16))*CC + h*CHD + l16*4;
      *(float4*)&Y[gbase] = o4;
    }

    // ---- state updates (W1/b1: column t is private; W2/b2: (q4,d64) partition)
    {
      float le15 = sTok[15];
      float cg[16]; float bsum = 0.f;
      #pragma unroll
      for (int j=0;j<16;j++){ cg[j] = le15*sLr[j]*sG1[j*260+t]; bsum += cg[j]; }
      sb1[t] -= bsum;
      #pragma unroll 4
      for (int d0=0; d0<64; d0+=4){
        float s0=0.f,s1=0.f,s2=0.f,s3=0.f;
        #pragma unroll
        for (int j=0;j<16;j++){
          float4 xk = *(const float4*)&sXK[j*68+d0];
          s0 += xk.x*cg[j]; s1 += xk.y*cg[j]; s2 += xk.z*cg[j]; s3 += xk.w*cg[j];
        }
        sW1[(d0+0)*256+t] -= s0;
        sW1[(d0+1)*256+t] -= s1;
        sW1[(d0+2)*256+t] -= s2;
        sW1[(d0+3)*256+t] -= s3;
      }
    }
    {
      float le15 = sTok[15];
      float cg[16]; float bsum = 0.f;
      #pragma unroll
      for (int j=0;j<16;j++){ cg[j] = le15*sLr[j]*sG2[j*68+d64]; bsum += cg[j]; }
      if (q4 == 0) sb2[d64] -= bsum;
      #pragma unroll 4
      for (int m=0; m<16; m++){
        int f0 = (q4*16+m)*4;
        float s0=0.f,s1=0.f,s2=0.f,s3=0.f;
        #pragma unroll
        for (int j=0;j<16;j++){
          float4 x2 = *(const float4*)&sX2[j*260+f0];
          s0 += x2.x*cg[j]; s1 += x2.y*cg[j]; s2 += x2.z*cg[j]; s3 += x2.w*cg[j];
        }
        sW2[(f0+0)*65+d64] -= s0;
        sW2[(f0+1)*65+d64] -= s1;
        sW2[(f0+2)*65+d64] -= s2;
        sW2[(f0+3)*65+d64] -= s3;
      }
    }
    __syncthreads();
  }
}

// ---------------- post layernorm over C=1024 --------------------------------
__global__ __launch_bounds__(256) void postln_kernel(
    const float* __restrict__ X, const float* __restrict__ g,
    const float* __restrict__ b, float* __restrict__ O)
{
  __shared__ float rs[8], rss[8], stats[2];
  int row = blockIdx.x, t = threadIdx.x;
  float4 x = ((const float4*)(X + (size_t)row*CC))[t];
  float s  = x.x+x.y+x.z+x.w;
  float ss = x.x*x.x + x.y*x.y + x.z*x.z + x.w*x.w;
  #pragma unroll
  for (int o=16;o;o>>=1){ s += __shfl_xor_sync(0xffffffffu, s, o); ss += __shfl_xor_sync(0xffffffffu, ss, o); }
  if ((t & 31) == 0){ rs[t>>5] = s; rss[t>>5] = ss; }
  __syncthreads();
  if (t == 0){
    float a=0.f, c=0.f;
    #pragma unroll
    for (int w=0;w<8;w++){ a += rs[w]; c += rss[w]; }
    stats[0] = a*(1.0f/1024.0f);
    stats[1] = c*(1.0f/1024.0f);
  }
  __syncthreads();
  float mu = stats[0];
  float var = stats[1] - mu*mu;
  float rstd = rsqrtf(var + 1e-6f);
  float4 gv = ((const float4*)g)[t];
  float4 bv = ((const float4*)b)[t];
  float4 o4;
  o4.x = gv.x*(x.x-mu)*rstd + bv.x;
  o4.y = gv.y*(x.y-mu)*rstd + bv.y;
  o4.z = gv.z*(x.z-mu)*rstd + bv.z;
  o4.w = gv.w*(x.w-mu)*rstd + bv.w;
  ((float4*)(O + (size_t)row*CC))[t] = o4;
}

// ---------------- launch -----------------------------------------------------
extern "C" void kernel_launch(void* const* d_in, const int* in_sizes, int n_in,
                              void* d_out, int out_size)
{
  const float* hs  = (const float*)d_in[0];
  const float* wq  = (const float*)d_in[1];
  const float* wk  = (const float*)d_in[2];
  const float* wv  = (const float*)d_in[3];
  const float* wo  = (const float*)d_in[4];
  const float* lti = (const float*)d_in[5];
  const float* lrw = (const float*)d_in[6];
  const float* lrb = (const float*)d_in[7];
  const float* tnw = (const float*)d_in[8];
  const float* tnb = (const float*)d_in[9];
  const float* pnw = (const float*)d_in[10];
  const float* pnb = (const float*)d_in[11];
  const float* W1  = (const float*)d_in[12];
  const float* b1  = (const float*)d_in[13];
  const float* W2  = (const float*)d_in[14];
  const float* b2  = (const float*)d_in[15];
  float* out = (float*)d_out;

  float *pQ, *pK, *pV, *pY, *pLR;
  cudaGetSymbolAddress((void**)&pQ,  g_Q);
  cudaGetSymbolAddress((void**)&pK,  g_K);
  cudaGetSymbolAddress((void**)&pV,  g_V);
  cudaGetSymbolAddress((void**)&pY,  g_Y);
  cudaGetSymbolAddress((void**)&pLR, g_LR);

  cudaFuncSetAttribute(scan_kernel, cudaFuncAttributeMaxDynamicSharedMemorySize, SCAN_SMEM);

  const int M = CB*CL;  // 8192
  gemm_nt64<<<(M/64)*(CC/64), 256>>>(hs, wq, pQ, M, CC, CC);
  gemm_nt64<<<(M/64)*(CC/64), 256>>>(hs, wk, pK, M, CC, CC);
  gemm_nt64<<<(M/64)*(CC/64), 256>>>(hs, wv, pV, M, CC, CC);
  rope_kernel<<<(2*CB*CL*CNH*(CHD/2))/256, 256>>>(pQ, pK);
  lr_kernel<<<CB*CL, 256>>>(hs, lrw, lrb, pLR);
  scan_kernel<<<CB*CNH, 256, SCAN_SMEM>>>(pQ, pK, pV, pLR, lti, tnw, tnb,
                                          W1, b1, W2, b2, pY);
  postln_kernel<<<CB*CL, 256>>>(pY, pnw, pnb, pQ);
  gemm_nt64<<<(M/64)*(CC/64), 256>>>(pQ, wo, out, M, CC, CC);
}

// round 4
// speedup vs baseline: 1.3020x; 1.3020x over previous
#include <cuda_runtime.h>
#include <math.h>
#include <stdint.h>

#define CB 4
#define CL 2048
#define CC 1024
#define CNH 16
#define CHD 64
#define CK 16
#define CF4 256
#define CNC 128

// ---------------- scratch (device globals; no allocations allowed) ----------
__device__ float g_Q [CB*CL*CC];
__device__ float g_K [CB*CL*CC];
__device__ float g_V [CB*CL*CC];
__device__ float g_Y [CB*CL*CC];
__device__ float g_LR[CB*CNH*CL];

// ---------------- math helpers ----------------------------------------------
__device__ __forceinline__ float gelu_f(float x){
  float x2 = x*x;
  float t = tanhf(0.79788456f*x*(1.0f+0.044715f*x2));
  return 0.5f*x*(1.0f+t);
}
__device__ __forceinline__ float gelu_bwd_f(float x){
  float x2 = x*x;
  float t = tanhf(0.79788456f*x*(1.0f+0.044715f*x2));
  return 0.5f*x*((1.0f-t*t)*(0.79788456f + 0.1070322243f*x2)) + 0.5f*(1.0f+t);
}

__device__ __forceinline__ uint32_t f2tf(float f){
  uint32_t u; asm("cvt.rna.tf32.f32 %0, %1;" : "=r"(u) : "f"(f)); return u;
}
__device__ __forceinline__ void sts_tf4(uint32_t* p, float4 v){
  uint4 u; u.x=f2tf(v.x); u.y=f2tf(v.y); u.z=f2tf(v.z); u.w=f2tf(v.w);
  *(uint4*)p = u;
}
__device__ __forceinline__ void mma_tf32(float* c, const uint32_t* a, const uint32_t* b){
  asm volatile("mma.sync.aligned.m16n8k8.row.col.f32.tf32.tf32.f32 "
    "{%0,%1,%2,%3}, {%4,%5,%6,%7}, {%8,%9}, {%0,%1,%2,%3};"
    : "+f"(c[0]),"+f"(c[1]),"+f"(c[2]),"+f"(c[3])
    : "r"(a[0]),"r"(a[1]),"r"(a[2]),"r"(a[3]), "r"(b[0]),"r"(b[1]));
}

// ------------ tf32 tensor-core GEMM: C[M,N] = A[M,K] * B[N,K]^T -------------
// CTA tile 128x128, BK=16, 8 warps (4m x 2n), warp tile 32x64.
// smem stride 20 => all fragment LDS patterns conflict-free.
__global__ __launch_bounds__(256) void gemm_tf32(
    const float* __restrict__ A, const float* __restrict__ B,
    float* __restrict__ C, int M, int N, int Kd)
{
  __shared__ uint32_t As[2][128*20];
  __shared__ uint32_t Bs[2][128*20];
  const int tid  = threadIdx.x;
  const int nt   = N >> 7;
  const int by   = blockIdx.x / nt;
  const int bx   = blockIdx.x % nt;
  const int wid  = tid >> 5;
  const int lane = tid & 31;
  const int wm   = (wid & 3) * 32;
  const int wn   = (wid >> 2) * 64;
  const int g    = lane >> 2;
  const int kq   = lane & 3;

  const int lrow = tid >> 1;
  const int lk   = (tid & 1) * 8;
  const float* Ag = A + (size_t)(by*128 + lrow)*Kd + lk;
  const float* Bg = B + (size_t)(bx*128 + lrow)*Kd + lk;
  const int sidx = lrow*20 + lk;

  float acc[2][8][4];
  #pragma unroll
  for (int i=0;i<2;i++)
    #pragma unroll
    for (int j=0;j<8;j++)
      #pragma unroll
      for (int k=0;k<4;k++) acc[i][j][k]=0.f;

  const int nk = Kd >> 4;
  float4 pa0 = *(const float4*)(Ag);
  float4 pa1 = *(const float4*)(Ag+4);
  float4 pb0 = *(const float4*)(Bg);
  float4 pb1 = *(const float4*)(Bg+4);
  sts_tf4(&As[0][sidx],   pa0);
  sts_tf4(&As[0][sidx+4], pa1);
  sts_tf4(&Bs[0][sidx],   pb0);
  sts_tf4(&Bs[0][sidx+4], pb1);

  for (int kt = 0; kt < nk; kt++){
    __syncthreads();
    if (kt+1 < nk){
      const float* Ap = Ag + (kt+1)*16;
      const float* Bp = Bg + (kt+1)*16;
      pa0 = *(const float4*)Ap; pa1 = *(const float4*)(Ap+4);
      pb0 = *(const float4*)Bp; pb1 = *(const float4*)(Bp+4);
    }
    const uint32_t* Ab = As[kt&1];
    const uint32_t* Bb = Bs[kt&1];
    #pragma unroll
    for (int k8 = 0; k8 < 2; k8++){
      const int ko = k8*8 + kq;
      uint32_t a[2][4], bf[8][2];
      #pragma unroll
      for (int fm=0; fm<2; fm++){
        int r = wm + fm*16 + g;
        a[fm][0] = Ab[r*20 + ko];
        a[fm][1] = Ab[(r+8)*20 + ko];
        a[fm][2] = Ab[r*20 + ko + 4];
        a[fm][3] = Ab[(r+8)*20 + ko + 4];
      }
      #pragma unroll
      for (int fn=0; fn<8; fn++){
        int r = wn + fn*8 + g;
        bf[fn][0] = Bb[r*20 + ko];
        bf[fn][1] = Bb[r*20 + ko + 4];
      }
      #pragma unroll
      for (int fm=0; fm<2; fm++)
        #pragma unroll
        for (int fn=0; fn<8; fn++)
          mma_tf32(acc[fm][fn], a[fm], bf[fn]);
    }
    if (kt+1 < nk){
      uint32_t* Aw = As[(kt+1)&1];
      uint32_t* Bw = Bs[(kt+1)&1];
      sts_tf4(&Aw[sidx],   pa0);
      sts_tf4(&Aw[sidx+4], pa1);
      sts_tf4(&Bw[sidx],   pb0);
      sts_tf4(&Bw[sidx+4], pb1);
    }
  }

  #pragma unroll
  for (int fm=0; fm<2; fm++){
    int r0 = by*128 + wm + fm*16 + g;
    #pragma unroll
    for (int fn=0; fn<8; fn++){
      int c = bx*128 + wn + fn*8 + kq*2;
      *(float2*)&C[(size_t)r0*N + c]     = make_float2(acc[fm][fn][0], acc[fm][fn][1]);
      *(float2*)&C[(size_t)(r0+8)*N + c] = make_float2(acc[fm][fn][2], acc[fm][fn][3]);
    }
  }
}

// ---------------- RoPE (interleaved pairs, pos = l mod 16) ------------------
__global__ __launch_bounds__(256) void rope_kernel(float* __restrict__ Q, float* __restrict__ Kt)
{
  const int PAIRS = CB*CL*CNH*(CHD/2); // 4194304
  int i = blockIdx.x*blockDim.x + threadIdx.x;
  if (i >= 2*PAIRS) return;
  float* T = (i < PAIRS) ? Q : Kt;
  int j = (i < PAIRS) ? i : (i - PAIRS);
  int p = j & 31; j >>= 5;
  int h = j & 15; j >>= 4;
  int l = j & 2047;
  int b = j >> 11;
  float pos = (float)(l & 15);
  float ang = pos * exp2f(-(float)p * (13.287712379549449f/32.0f));
  float sn, cs;
  sincosf(ang, &sn, &cs);
  size_t base = ((size_t)(b*CL + l))*CC + h*CHD + 2*p;
  float2 x = *(float2*)&T[base];
  float2 y;
  y.x = x.x*cs - x.y*sn;
  y.y = x.y*cs + x.x*sn;
  *(float2*)&T[base] = y;
}

// ---------------- ttt_lr sigmoid dots: lr[b,h,l] ----------------------------
__global__ __launch_bounds__(256) void lr_kernel(
    const float* __restrict__ hs, const float* __restrict__ w,
    const float* __restrict__ bias, float* __restrict__ lr)
{
  __shared__ float row[CC];
  int bl = blockIdx.x;            // b*L + l
  int tid = threadIdx.x;
  ((float4*)row)[tid] = ((const float4*)(hs + (size_t)bl*CC))[tid];
  __syncthreads();
  int h = tid >> 4, ln = tid & 15;
  float acc = 0.f;
  for (int c0 = ln*4; c0 < CC; c0 += 64){
    float4 r = *(const float4*)&row[c0];
    float4 wv = *(const float4*)&w[h*CC + c0];
    acc += r.x*wv.x + r.y*wv.y + r.z*wv.z + r.w*wv.w;
  }
  #pragma unroll
  for (int o=8;o;o>>=1) acc += __shfl_xor_sync(0xffffffffu, acc, o);
  if (ln == 0){
    int b = bl >> 11, l = bl & 2047;
    float v = acc + bias[h];
    lr[((size_t)(b*CNH + h))*CL + l] = 1.0f/(1.0f + expf(-v));
  }
}

// ---------------- scan kernel: one CTA per (b,h), all state in smem ---------
#define OW1 0        /* [64][256]           */
#define OW2 16384    /* [256][65]           */
#define OB1 33024    /* [256]               */
#define OB2 33280    /* [64]                */
#define OLW 33344    /* [64] ln weight      */
#define OLB 33408    /* [64] ln bias        */
#define OXQ 33472    /* [16][68]            */
#define OXK 34560
#define OXV 35648
#define OZ2 36736    /* [16][68] Z2/Z2bar   */
#define OG2 37824    /* [16][68] gZ2        */
#define OCC 38912    /* [16][17] coeffs     */
#define OTK 39184    /* [16] token_idx      */
#define OLR 39200    /* [16] lr vec         */
#define OZ1 39216    /* [16][260] Z1/X2bar  */
#define OX2 43376    /* [16][260] X2        */
#define OG1 47536    /* [16][260] gZ1       */
#define SCAN_FLOATS 51696
#define SCAN_SMEM (SCAN_FLOATS*4)

__global__ __launch_bounds__(256) void scan_kernel(
  const float* __restrict__ Q, const float* __restrict__ Kx, const float* __restrict__ V,
  const float* __restrict__ LR, const float* __restrict__ lti,
  const float* __restrict__ lnw, const float* __restrict__ lnb,
  const float* __restrict__ W1g, const float* __restrict__ b1g,
  const float* __restrict__ W2g, const float* __restrict__ b2g,
  float* __restrict__ Y)
{
  extern __shared__ float sm[];
  const int t = threadIdx.x;
  const int bh = blockIdx.x;
  const int b = bh >> 4, h = bh & 15;
  float* sW1 = sm + OW1;
  float* sW2 = sm + OW2;
  float* sb1 = sm + OB1;
  float* sb2 = sm + OB2;
  float* sLW = sm + OLW;
  float* sLB = sm + OLB;
  float* sXQ = sm + OXQ;
  float* sXK = sm + OXK;
  float* sXV = sm + OXV;
  float* sZ2 = sm + OZ2;
  float* sG2 = sm + OG2;
  float* sC  = sm + OCC;
  float* sTok= sm + OTK;
  float* sLr = sm + OLR;
  float* sZ1 = sm + OZ1;
  float* sX2 = sm + OX2;
  float* sG1 = sm + OG1;

  for (int idx = t; idx < 16384; idx += 256) sW1[idx] = W1g[h*16384 + idx];
  for (int idx = t; idx < 16384; idx += 256) {
    int f = idx >> 6, d = idx & 63;
    sW2[f*65+d] = W2g[h*16384 + idx];
  }
  sb1[t] = b1g[h*256+t];
  if (t < 64) { sb2[t] = b2g[h*64+t]; sLW[t] = lnw[h*64+t]; sLB[t] = lnb[h*64+t]; }
  if (t < 16) sTok[t] = fmaxf(1.0f/(float)(t+1) + lti[t], 0.0f);
  __syncthreads();

  const int i16 = t >> 4, l16 = t & 15;
  const int d64 = t & 63, q4 = t >> 6;

  for (int n = 0; n < CNC; n++) {
    const int l0 = n*16;
    {
      size_t gbase = ((size_t)(b*CL + l0 + i16))*CC + h*CHD + l16*4;
      int sbase = i16*68 + l16*4;
      *(float4*)&sXQ[sbase] = *(const float4*)&Q [gbase];
      *(float4*)&sXK[sbase] = *(const float4*)&Kx[gbase];
      *(float4*)&sXV[sbase] = *(const float4*)&V [gbase];
    }
    if (t < 16) sLr[t] = LR[((size_t)bh)*CL + l0 + t] * (1.0f/64.0f);
    __syncthreads();

    // Z1 = XK@W1 + b1 ; X2 = gelu(Z1)
    {
      float acc[16];
      #pragma unroll
      for (int i=0;i<16;i++) acc[i] = sb1[t];
      #pragma unroll 4
      for (int d0=0; d0<64; d0+=4) {
        float w0 = sW1[(d0+0)*256+t], w1 = sW1[(d0+1)*256+t];
        float w2 = sW1[(d0+2)*256+t], w3 = sW1[(d0+3)*256+t];
        #pragma unroll
        for (int i=0;i<16;i++) {
          float4 xk = *(const float4*)&sXK[i*68+d0];
          acc[i] += xk.x*w0 + xk.y*w1 + xk.z*w2 + xk.w*w3;
        }
      }
      #pragma unroll
      for (int i=0;i<16;i++){ float z = acc[i]; sZ1[i*260+t] = z; sX2[i*260+t] = gelu_f(z); }
    }
    __syncthreads();

    // Z2 = X2@W2 + b2
    {
      float a2[4];
      #pragma unroll
      for (int r=0;r<4;r++) a2[r] = sb2[d64];
      #pragma unroll 4
      for (int f0=0; f0<256; f0+=4) {
        float w0 = sW2[(f0+0)*65+d64], w1 = sW2[(f0+1)*65+d64];
        float w2 = sW2[(f0+2)*65+d64], w3 = sW2[(f0+3)*65+d64];
        #pragma unroll
        for (int r=0;r<4;r++) {
          float4 x = *(const float4*)&sX2[(q4*4+r)*260+f0];
          a2[r] += x.x*w0 + x.y*w1 + x.z*w2 + x.w*w3;
        }
      }
      #pragma unroll
      for (int r=0;r<4;r++) sZ2[(q4*4+r)*68+d64] = a2[r];
    }
    // Attn1 coeffs
    {
      float c = 0.0f;
      if (l16 <= i16) {
        float a = 0.0f;
        #pragma unroll
        for (int d0=0; d0<64; d0+=4) {
          float4 xq = *(const float4*)&sXQ[i16*68+d0];
          float4 xk = *(const float4*)&sXK[l16*68+d0];
          a += xq.x*xk.x + xq.y*xk.y + xq.z*xk.z + xq.w*xk.w;
        }
        c = sTok[i16]*sLr[l16]*(a + 1.0f);
      }
      sC[i16*17+l16] = c;
    }
    __syncthreads();

    // gZ2 = ln_fused_l2_bwd(Z2, XV-XK)
    {
      int base = i16*68 + l16*4;
      float4 x = *(const float4*)&sZ2[base];
      float s  = x.x+x.y+x.z+x.w;
      float ss = x.x*x.x + x.y*x.y + x.z*x.z + x.w*x.w;
      #pragma unroll
      for (int o=8;o;o>>=1){ s += __shfl_xor_sync(0xffffffffu, s, o); ss += __shfl_xor_sync(0xffffffffu, ss, o); }
      float mu = s*(1.0f/64.0f);
      float var = ss*(1.0f/64.0f) - mu*mu;
      float rstd = rsqrtf(var + 1e-6f);
      float4 xh;
      xh.x=(x.x-mu)*rstd; xh.y=(x.y-mu)*rstd; xh.z=(x.z-mu)*rstd; xh.w=(x.w-mu)*rstd;
      float4 g  = *(const float4*)&sLW[l16*4];
      float4 bb = *(const float4*)&sLB[l16*4];
      float4 xv = *(const float4*)&sXV[base];
      float4 xk = *(const float4*)&sXK[base];
      float4 go;
      go.x = (g.x*xh.x + bb.x - (xv.x - xk.x))*g.x;
      go.y = (g.y*xh.y + bb.y - (xv.y - xk.y))*g.y;
      go.z = (g.z*xh.z + bb.z - (xv.z - xk.z))*g.z;
      go.w = (g.w*xh.w + bb.w - (xv.w - xk.w))*g.w;
      float sg  = go.x+go.y+go.z+go.w;
      float sgx = go.x*xh.x + go.y*xh.y + go.z*xh.z + go.w*xh.w;
      #pragma unroll
      for (int o=8;o;o>>=1){ sg += __shfl_xor_sync(0xffffffffu, sg, o); sgx += __shfl_xor_sync(0xffffffffu, sgx, o); }
      float k1 = rstd*(1.0f/64.0f);
      float4 o4;
      o4.x = (64.0f*go.x - sg - xh.x*sgx)*k1;
      o4.y = (64.0f*go.y - sg - xh.y*sgx)*k1;
      o4.z = (64.0f*go.z - sg - xh.z*sgx)*k1;
      o4.w = (64.0f*go.w - sg - xh.w*sgx)*k1;
      *(float4*)&sG2[base] = o4;
    }
    __syncthreads();

    // gZ1 = (gZ2 @ W2^T) * gelu_bwd(Z1)
    {
      float acc[16];
      #pragma unroll
      for (int i=0;i<16;i++) acc[i]=0.f;
      #pragma unroll 4
      for (int d0=0; d0<64; d0+=4) {
        float w0 = sW2[t*65+d0+0], w1 = sW2[t*65+d0+1];
        float w2 = sW2[t*65+d0+2], w3 = sW2[t*65+d0+3];
        #pragma unroll
        for (int i=0;i<16;i++) {
          float4 gz = *(const float4*)&sG2[i*68+d0];
          acc[i] += gz.x*w0 + gz.y*w1 + gz.z*w2 + gz.w*w3;
        }
      }
      #pragma unroll
      for (int i=0;i<16;i++) sG1[i*260+t] = acc[i]*gelu_bwd_f(sZ1[i*260+t]);
    }

    // Z1_bar -> X2_bar = gelu(Z1_bar)
    {
      float acc[16];
      #pragma unroll
      for (int i=0;i<16;i++) acc[i] = sb1[t];
      #pragma unroll 4
      for (int d0=0; d0<64; d0+=4) {
        float w0 = sW1[(d0+0)*256+t], w1 = sW1[(d0+1)*256+t];
        float w2 = sW1[(d0+2)*256+t], w3 = sW1[(d0+3)*256+t];
        #pragma unroll
        for (int i=0;i<16;i++) {
          float4 xq = *(const float4*)&sXQ[i*68+d0];
          acc[i] += xq.x*w0 + xq.y*w1 + xq.z*w2 + xq.w*w3;
        }
      }
      float gz[16];
      #pragma unroll
      for (int j=0;j<16;j++) gz[j] = sG1[j*260+t];
      #pragma unroll
      for (int i=0;i<16;i++){
        float a = acc[i];
        #pragma unroll
        for (int j=0;j<=i;j++) a -= sC[i*17+j]*gz[j];
        sZ1[i*260+t] = gelu_f(a);
      }
    }
    __syncthreads();

    // Attn2 coeffs
    {
      float c = 0.0f;
      if (l16 <= i16) {
        float a = 0.0f;
        #pragma unroll 8
        for (int f0=0; f0<256; f0+=4) {
          float4 xb = *(const float4*)&sZ1[i16*260+f0];
          float4 x2 = *(const float4*)&sX2[l16*260+f0];
          a += xb.x*x2.x + xb.y*x2.y + xb.z*x2.z + xb.w*x2.w;
        }
        c = sTok[i16]*sLr[l16]*(a + 1.0f);
      }
      sC[i16*17+l16] = c;
    }
    __syncthreads();

    // Z2_bar = X2bar@W2 + b2 - corrections
    {
      float a2[4];
      #pragma unroll
      for (int r=0;r<4;r++) a2[r] = sb2[d64];
      #pragma unroll 4
      for (int f0=0; f0<256; f0+=4) {
        float w0 = sW2[(f0+0)*65+d64], w1 = sW2[(f0+1)*65+d64];
        float w2 = sW2[(f0+2)*65+d64], w3 = sW2[(f0+3)*65+d64];
        #pragma unroll
        for (int r=0;r<4;r++) {
          float4 x = *(const float4*)&sZ1[(q4*4+r)*260+f0];
          a2[r] += x.x*w0 + x.y*w1 + x.z*w2 + x.w*w3;
        }
      }
      float gz[16];
      #pragma unroll
      for (int j=0;j<16;j++) gz[j] = sG2[j*68+d64];
      #pragma unroll
      for (int r=0;r<4;r++){
        int i = q4*4+r;
        float a = a2[r];
        for (int j=0;j<=i;j++) a -= sC[i*17+j]*gz[j];
        sZ2[i*68+d64] = a;
      }
    }
    __syncthreads();

    // output: Y = XQ + ln_fwd(Z2_bar)
    {
      int base = i16*68 + l16*4;
      float4 x = *(const float4*)&sZ2[base];
      float s  = x.x+x.y+x.z+x.w;
      float ss = x.x*x.x + x.y*x.y + x.z*x.z + x.w*x.w;
      #pragma unroll
      for (int o=8;o;o>>=1){ s += __shfl_xor_sync(0xffffffffu, s, o); ss += __shfl_xor_sync(0xffffffffu, ss, o); }
      float mu = s*(1.0f/64.0f);
      float var = ss*(1.0f/64.0f) - mu*mu;
      float rstd = rsqrtf(var + 1e-6f);
      float4 g  = *(const float4*)&sLW[l16*4];
      float4 bb = *(const float4*)&sLB[l16*4];
      float4 xq = *(const float4*)&sXQ[base];
      float4 o4;
      o4.x = g.x*(x.x-mu)*rstd + bb.x + xq.x;
      o4.y = g.y*(x.y-mu)*rstd + bb.y + xq.y;
      o4.z = g.z*(x.z-mu)*rstd + bb.z + xq.z;
      o4.w = g.w*(x.w-mu)*rstd + bb.w + xq.w;
      size_t gbase = ((size_t)(b*CL + l0 + i16))*CC + h*CHD + l16*4;
      *(float4*)&Y[gbase] = o4;
    }

    // state updates
    {
      float le15 = sTok[15];
      float cg[16]; float bsum = 0.f;
      #pragma unroll
      for (int j=0;j<16;j++){ cg[j] = le15*sLr[j]*sG1[j*260+t]; bsum += cg[j]; }
      sb1[t] -= bsum;
      #pragma unroll 4
      for (int d0=0; d0<64; d0+=4){
        float s0=0.f,s1=0.f,s2=0.f,s3=0.f;
        #pragma unroll
        for (int j=0;j<16;j++){
          float4 xk = *(const float4*)&sXK[j*68+d0];
          s0 += xk.x*cg[j]; s1 += xk.y*cg[j]; s2 += xk.z*cg[j]; s3 += xk.w*cg[j];
        }
        sW1[(d0+0)*256+t] -= s0;
        sW1[(d0+1)*256+t] -= s1;
        sW1[(d0+2)*256+t] -= s2;
        sW1[(d0+3)*256+t] -= s3;
      }
    }
    {
      float le15 = sTok[15];
      float cg[16]; float bsum = 0.f;
      #pragma unroll
      for (int j=0;j<16;j++){ cg[j] = le15*sLr[j]*sG2[j*68+d64]; bsum += cg[j]; }
      if (q4 == 0) sb2[d64] -= bsum;
      #pragma unroll 4
      for (int m=0; m<16; m++){
        int f0 = (q4*16+m)*4;
        float s0=0.f,s1=0.f,s2=0.f,s3=0.f;
        #pragma unroll
        for (int j=0;j<16;j++){
          float4 x2 = *(const float4*)&sX2[j*260+f0];
          s0 += x2.x*cg[j]; s1 += x2.y*cg[j]; s2 += x2.z*cg[j]; s3 += x2.w*cg[j];
        }
        sW2[(f0+0)*65+d64] -= s0;
        sW2[(f0+1)*65+d64] -= s1;
        sW2[(f0+2)*65+d64] -= s2;
        sW2[(f0+3)*65+d64] -= s3;
      }
    }
    __syncthreads();
  }
}

// ---------------- post layernorm over C=1024 --------------------------------
__global__ __launch_bounds__(256) void postln_kernel(
    const float* __restrict__ X, const float* __restrict__ g,
    const float* __restrict__ b, float* __restrict__ O)
{
  __shared__ float rs[8], rss[8], stats[2];
  int row = blockIdx.x, t = threadIdx.x;
  float4 x = ((const float4*)(X + (size_t)row*CC))[t];
  float s  = x.x+x.y+x.z+x.w;
  float ss = x.x*x.x + x.y*x.y + x.z*x.z + x.w*x.w;
  #pragma unroll
  for (int o=16;o;o>>=1){ s += __shfl_xor_sync(0xffffffffu, s, o); ss += __shfl_xor_sync(0xffffffffu, ss, o); }
  if ((t & 31) == 0){ rs[t>>5] = s; rss[t>>5] = ss; }
  __syncthreads();
  if (t == 0){
    float a=0.f, c=0.f;
    #pragma unroll
    for (int w=0;w<8;w++){ a += rs[w]; c += rss[w]; }
    stats[0] = a*(1.0f/1024.0f);
    stats[1] = c*(1.0f/1024.0f);
  }
  __syncthreads();
  float mu = stats[0];
  float var = stats[1] - mu*mu;
  float rstd = rsqrtf(var + 1e-6f);
  float4 gv = ((const float4*)g)[t];
  float4 bv = ((const float4*)b)[t];
  float4 o4;
  o4.x = gv.x*(x.x-mu)*rstd + bv.x;
  o4.y = gv.y*(x.y-mu)*rstd + bv.y;
  o4.z = gv.z*(x.z-mu)*rstd + bv.z;
  o4.w = gv.w*(x.w-mu)*rstd + bv.w;
  ((float4*)(O + (size_t)row*CC))[t] = o4;
}

// ---------------- launch -----------------------------------------------------
extern "C" void kernel_launch(void* const* d_in, const int* in_sizes, int n_in,
                              void* d_out, int out_size)
{
  const float* hs  = (const float*)d_in[0];
  const float* wq  = (const float*)d_in[1];
  const float* wk  = (const float*)d_in[2];
  const float* wv  = (const float*)d_in[3];
  const float* wo  = (const float*)d_in[4];
  const float* lti = (const float*)d_in[5];
  const float* lrw = (const float*)d_in[6];
  const float* lrb = (const float*)d_in[7];
  const float* tnw = (const float*)d_in[8];
  const float* tnb = (const float*)d_in[9];
  const float* pnw = (const float*)d_in[10];
  const float* pnb = (const float*)d_in[11];
  const float* W1  = (const float*)d_in[12];
  const float* b1  = (const float*)d_in[13];
  const float* W2  = (const float*)d_in[14];
  const float* b2  = (const float*)d_in[15];
  float* out = (float*)d_out;

  float *pQ, *pK, *pV, *pY, *pLR;
  cudaGetSymbolAddress((void**)&pQ,  g_Q);
  cudaGetSymbolAddress((void**)&pK,  g_K);
  cudaGetSymbolAddress((void**)&pV,  g_V);
  cudaGetSymbolAddress((void**)&pY,  g_Y);
  cudaGetSymbolAddress((void**)&pLR, g_LR);

  cudaFuncSetAttribute(scan_kernel, cudaFuncAttributeMaxDynamicSharedMemorySize, SCAN_SMEM);

  const int M = CB*CL;  // 8192
  const int GG = (M/128)*(CC/128);  // 512
  gemm_tf32<<<GG, 256>>>(hs, wq, pQ, M, CC, CC);
  gemm_tf32<<<GG, 256>>>(hs, wk, pK, M, CC, CC);
  gemm_tf32<<<GG, 256>>>(hs, wv, pV, M, CC, CC);
  rope_kernel<<<(2*CB*CL*CNH*(CHD/2))/256, 256>>>(pQ, pK);
  lr_kernel<<<CB*CL, 256>>>(hs, lrw, lrb, pLR);
  scan_kernel<<<CB*CNH, 256, SCAN_SMEM>>>(pQ, pK, pV, pLR, lti, tnw, tnb,
                                          W1, b1, W2, b2, pY);
  postln_kernel<<<CB*CL, 256>>>(pY, pnw, pnb, pQ);
  gemm_tf32<<<GG, 256>>>(pQ, wo, out, M, CC, CC);
}

// round 5
// speedup vs baseline: 1.4313x; 1.0993x over previous
#include <cuda_runtime.h>
#include <math.h>
#include <stdint.h>

#define CB 4
#define CL 2048
#define CC 1024
#define CNH 16
#define CHD 64
#define CK 16
#define CF4 256
#define CNC 128

// ---------------- scratch (device globals; no allocations allowed) ----------
__device__ float g_Q [CB*CL*CC];
__device__ float g_K [CB*CL*CC];
__device__ float g_V [CB*CL*CC];
__device__ float g_Y [CB*CL*CC];
__device__ float g_LR[CB*CNH*CL];

typedef unsigned long long u64t;

// ---------------- math helpers ----------------------------------------------
__device__ __forceinline__ float gelu_f(float x){
  float x2 = x*x;
  float t = tanhf(0.79788456f*x*(1.0f+0.044715f*x2));
  return 0.5f*x*(1.0f+t);
}
__device__ __forceinline__ float gelu_bwd_f(float x){
  float x2 = x*x;
  float t = tanhf(0.79788456f*x*(1.0f+0.044715f*x2));
  return 0.5f*x*((1.0f-t*t)*(0.79788456f + 0.1070322243f*x2)) + 0.5f*(1.0f+t);
}

// packed fp32x2 helpers (Blackwell FFMA2 path; exact fp32 semantics)
__device__ __forceinline__ u64t pk2(float x, float y){
  u64t r; asm("mov.b64 %0, {%1, %2};" : "=l"(r) : "f"(x), "f"(y)); return r;
}
__device__ __forceinline__ float2 upk(u64t v){
  float2 f; asm("mov.b64 {%0, %1}, %2;" : "=f"(f.x), "=f"(f.y) : "l"(v)); return f;
}
__device__ __forceinline__ u64t f2fma(u64t a, u64t b, u64t c){
  u64t d; asm("fma.rn.f32x2 %0, %1, %2, %3;" : "=l"(d) : "l"(a), "l"(b), "l"(c)); return d;
}

__device__ __forceinline__ uint32_t f2tf(float f){
  uint32_t u; asm("cvt.rna.tf32.f32 %0, %1;" : "=r"(u) : "f"(f)); return u;
}
__device__ __forceinline__ void sts_tf4(uint32_t* p, float4 v){
  uint4 u; u.x=f2tf(v.x); u.y=f2tf(v.y); u.z=f2tf(v.z); u.w=f2tf(v.w);
  *(uint4*)p = u;
}
__device__ __forceinline__ void mma_tf32(float* c, const uint32_t* a, const uint32_t* b){
  asm volatile("mma.sync.aligned.m16n8k8.row.col.f32.tf32.tf32.f32 "
    "{%0,%1,%2,%3}, {%4,%5,%6,%7}, {%8,%9}, {%0,%1,%2,%3};"
    : "+f"(c[0]),"+f"(c[1]),"+f"(c[2]),"+f"(c[3])
    : "r"(a[0]),"r"(a[1]),"r"(a[2]),"r"(a[3]), "r"(b[0]),"r"(b[1]));
}

// ------------ tf32 tensor-core GEMM: C[M,N] = A[M,K] * B[N,K]^T -------------
__global__ __launch_bounds__(256) void gemm_tf32(
    const float* __restrict__ A, const float* __restrict__ B,
    float* __restrict__ C, int M, int N, int Kd)
{
  __shared__ uint32_t As[2][128*20];
  __shared__ uint32_t Bs[2][128*20];
  const int tid  = threadIdx.x;
  const int nt   = N >> 7;
  const int by   = blockIdx.x / nt;
  const int bx   = blockIdx.x % nt;
  const int wid  = tid >> 5;
  const int lane = tid & 31;
  const int wm   = (wid & 3) * 32;
  const int wn   = (wid >> 2) * 64;
  const int g    = lane >> 2;
  const int kq   = lane & 3;

  const int lrow = tid >> 1;
  const int lk   = (tid & 1) * 8;
  const float* Ag = A + (size_t)(by*128 + lrow)*Kd + lk;
  const float* Bg = B + (size_t)(bx*128 + lrow)*Kd + lk;
  const int sidx = lrow*20 + lk;

  float acc[2][8][4];
  #pragma unroll
  for (int i=0;i<2;i++)
    #pragma unroll
    for (int j=0;j<8;j++)
      #pragma unroll
      for (int k=0;k<4;k++) acc[i][j][k]=0.f;

  const int nk = Kd >> 4;
  float4 pa0 = *(const float4*)(Ag);
  float4 pa1 = *(const float4*)(Ag+4);
  float4 pb0 = *(const float4*)(Bg);
  float4 pb1 = *(const float4*)(Bg+4);
  sts_tf4(&As[0][sidx],   pa0);
  sts_tf4(&As[0][sidx+4], pa1);
  sts_tf4(&Bs[0][sidx],   pb0);
  sts_tf4(&Bs[0][sidx+4], pb1);

  for (int kt = 0; kt < nk; kt++){
    __syncthreads();
    if (kt+1 < nk){
      const float* Ap = Ag + (kt+1)*16;
      const float* Bp = Bg + (kt+1)*16;
      pa0 = *(const float4*)Ap; pa1 = *(const float4*)(Ap+4);
      pb0 = *(const float4*)Bp; pb1 = *(const float4*)(Bp+4);
    }
    const uint32_t* Ab = As[kt&1];
    const uint32_t* Bb = Bs[kt&1];
    #pragma unroll
    for (int k8 = 0; k8 < 2; k8++){
      const int ko = k8*8 + kq;
      uint32_t a[2][4], bf[8][2];
      #pragma unroll
      for (int fm=0; fm<2; fm++){
        int r = wm + fm*16 + g;
        a[fm][0] = Ab[r*20 + ko];
        a[fm][1] = Ab[(r+8)*20 + ko];
        a[fm][2] = Ab[r*20 + ko + 4];
        a[fm][3] = Ab[(r+8)*20 + ko + 4];
      }
      #pragma unroll
      for (int fn=0; fn<8; fn++){
        int r = wn + fn*8 + g;
        bf[fn][0] = Bb[r*20 + ko];
        bf[fn][1] = Bb[r*20 + ko + 4];
      }
      #pragma unroll
      for (int fm=0; fm<2; fm++)
        #pragma unroll
        for (int fn=0; fn<8; fn++)
          mma_tf32(acc[fm][fn], a[fm], bf[fn]);
    }
    if (kt+1 < nk){
      uint32_t* Aw = As[(kt+1)&1];
      uint32_t* Bw = Bs[(kt+1)&1];
      sts_tf4(&Aw[sidx],   pa0);
      sts_tf4(&Aw[sidx+4], pa1);
      sts_tf4(&Bw[sidx],   pb0);
      sts_tf4(&Bw[sidx+4], pb1);
    }
  }

  #pragma unroll
  for (int fm=0; fm<2; fm++){
    int r0 = by*128 + wm + fm*16 + g;
    #pragma unroll
    for (int fn=0; fn<8; fn++){
      int c = bx*128 + wn + fn*8 + kq*2;
      *(float2*)&C[(size_t)r0*N + c]     = make_float2(acc[fm][fn][0], acc[fm][fn][1]);
      *(float2*)&C[(size_t)(r0+8)*N + c] = make_float2(acc[fm][fn][2], acc[fm][fn][3]);
    }
  }
}

// ---------------- RoPE (interleaved pairs, pos = l mod 16) ------------------
__global__ __launch_bounds__(256) void rope_kernel(float* __restrict__ Q, float* __restrict__ Kt)
{
  const int PAIRS = CB*CL*CNH*(CHD/2);
  int i = blockIdx.x*blockDim.x + threadIdx.x;
  if (i >= 2*PAIRS) return;
  float* T = (i < PAIRS) ? Q : Kt;
  int j = (i < PAIRS) ? i : (i - PAIRS);
  int p = j & 31; j >>= 5;
  int h = j & 15; j >>= 4;
  int l = j & 2047;
  int b = j >> 11;
  float pos = (float)(l & 15);
  float ang = pos * exp2f(-(float)p * (13.287712379549449f/32.0f));
  float sn, cs;
  sincosf(ang, &sn, &cs);
  size_t base = ((size_t)(b*CL + l))*CC + h*CHD + 2*p;
  float2 x = *(float2*)&T[base];
  float2 y;
  y.x = x.x*cs - x.y*sn;
  y.y = x.y*cs + x.x*sn;
  *(float2*)&T[base] = y;
}

// ---------------- ttt_lr sigmoid dots: lr[b,h,l] ----------------------------
__global__ __launch_bounds__(256) void lr_kernel(
    const float* __restrict__ hs, const float* __restrict__ w,
    const float* __restrict__ bias, float* __restrict__ lr)
{
  __shared__ float row[CC];
  int bl = blockIdx.x;
  int tid = threadIdx.x;
  ((float4*)row)[tid] = ((const float4*)(hs + (size_t)bl*CC))[tid];
  __syncthreads();
  int h = tid >> 4, ln = tid & 15;
  float acc = 0.f;
  for (int c0 = ln*4; c0 < CC; c0 += 64){
    float4 r = *(const float4*)&row[c0];
    float4 wv = *(const float4*)&w[h*CC + c0];
    acc += r.x*wv.x + r.y*wv.y + r.z*wv.z + r.w*wv.w;
  }
  #pragma unroll
  for (int o=8;o;o>>=1) acc += __shfl_xor_sync(0xffffffffu, acc, o);
  if (ln == 0){
    int b = bl >> 11, l = bl & 2047;
    float v = acc + bias[h];
    lr[((size_t)(b*CNH + h))*CL + l] = 1.0f/(1.0f + expf(-v));
  }
}

// ---------------- scan kernel: one CTA per (b,h), all state in smem ---------
// W1T[c][d]: c in [0,256), stride 68  (W1T[c*68+d] = W1[d][c])
// W2T[d][f]: d in [0,64),  stride 260 (W2T[d*260+f] = W2[f][d])
#define OW1T 0        /* 256*68 = 17408 */
#define OW2T 17408    /* 64*260 = 16640 */
#define OB1  34048    /* 256 */
#define OB2  34304    /* 64  */
#define OLW  34368    /* 64  */
#define OLB  34432    /* 64  */
#define OXQ  34496    /* 16*68 */
#define OXK  35584
#define OXV  36672
#define OZ2  37760    /* 16*68 */
#define OG2  38848    /* 16*68 */
#define OCC  39936    /* 16*17 */
#define OTK  40208    /* 16 */
#define OLR  40224    /* 16 */
#define OZ1  40240    /* 16*260 */
#define OX2  44400
#define OG1  48560
#define SCAN_FLOATS 52720
#define SCAN_SMEM (SCAN_FLOATS*4)

__global__ __launch_bounds__(256) void scan_kernel(
  const float* __restrict__ Q, const float* __restrict__ Kx, const float* __restrict__ V,
  const float* __restrict__ LR, const float* __restrict__ lti,
  const float* __restrict__ lnw, const float* __restrict__ lnb,
  const float* __restrict__ W1g, const float* __restrict__ b1g,
  const float* __restrict__ W2g, const float* __restrict__ b2g,
  float* __restrict__ Y)
{
  extern __shared__ float sm[];
  const int t = threadIdx.x;
  const int bh = blockIdx.x;
  const int b = bh >> 4, h = bh & 15;
  float* sW1T = sm + OW1T;
  float* sW2T = sm + OW2T;
  float* sb1 = sm + OB1;
  float* sb2 = sm + OB2;
  float* sLW = sm + OLW;
  float* sLB = sm + OLB;
  float* sXQ = sm + OXQ;
  float* sXK = sm + OXK;
  float* sXV = sm + OXV;
  float* sZ2 = sm + OZ2;
  float* sG2 = sm + OG2;
  float* sC  = sm + OCC;
  float* sTok= sm + OTK;
  float* sLr = sm + OLR;
  float* sZ1 = sm + OZ1;
  float* sX2 = sm + OX2;
  float* sG1 = sm + OG1;

  // init state (transposed layouts)
  for (int idx = t; idx < 16384; idx += 256) {
    int d = idx >> 8, c = idx & 255;            // W1[d][c]
    sW1T[c*68+d] = W1g[h*16384 + idx];
  }
  for (int idx = t; idx < 16384; idx += 256) {
    int f = idx >> 6, d = idx & 63;             // W2[f][d]
    sW2T[d*260+f] = W2g[h*16384 + idx];
  }
  sb1[t] = b1g[h*256+t];
  if (t < 64) { sb2[t] = b2g[h*64+t]; sLW[t] = lnw[h*64+t]; sLB[t] = lnb[h*64+t]; }
  if (t < 16) sTok[t] = fmaxf(1.0f/(float)(t+1) + lti[t], 0.0f);
  __syncthreads();

  const int i16 = t >> 4, l16 = t & 15;   // LN/out mapping
  const int d64 = t & 63, q4 = t >> 6;    // 64-col mapping
  const int fp2 = (t & 127) * 2, rh = t >> 7;  // gZ1 mapping (2 cols, 8 rows)

  for (int n = 0; n < CNC; n++) {
    const int l0 = n*16;
    {
      size_t gbase = ((size_t)(b*CL + l0 + i16))*CC + h*CHD + l16*4;
      int sbase = i16*68 + l16*4;
      *(float4*)&sXQ[sbase] = *(const float4*)&Q [gbase];
      *(float4*)&sXK[sbase] = *(const float4*)&Kx[gbase];
      *(float4*)&sXV[sbase] = *(const float4*)&V [gbase];
    }
    if (t < 16) sLr[t] = LR[((size_t)bh)*CL + l0 + t] * (1.0f/64.0f);
    __syncthreads();

    // ---- Z1 = XK@W1 + b1 ; X2 = gelu(Z1)  (thread t = column t, packed f32x2)
    {
      u64t acc[16];
      #pragma unroll
      for (int i=0;i<16;i++) acc[i]=0ULL;
      const float* wp = &sW1T[t*68];
      #pragma unroll 4
      for (int d0=0; d0<64; d0+=4) {
        float4 wv = *(const float4*)&wp[d0];
        u64t w01 = pk2(wv.x,wv.y), w23 = pk2(wv.z,wv.w);
        #pragma unroll
        for (int i=0;i<16;i++) {
          float4 xk = *(const float4*)&sXK[i*68+d0];
          acc[i] = f2fma(pk2(xk.x,xk.y), w01, acc[i]);
          acc[i] = f2fma(pk2(xk.z,xk.w), w23, acc[i]);
        }
      }
      float bb = sb1[t];
      #pragma unroll
      for (int i=0;i<16;i++){
        float2 p = upk(acc[i]);
        float z = p.x + p.y + bb;
        sZ1[i*260+t] = z; sX2[i*260+t] = gelu_f(z);
      }
    }
    __syncthreads();

    // ---- Z2 = X2@W2 + b2   (thread: col d64, rows q4*4..+4)
    {
      u64t a2[4];
      #pragma unroll
      for (int r=0;r<4;r++) a2[r]=0ULL;
      const float* wp = &sW2T[d64*260];
      #pragma unroll 4
      for (int f0=0; f0<256; f0+=4) {
        float4 wv = *(const float4*)&wp[f0];
        u64t w01 = pk2(wv.x,wv.y), w23 = pk2(wv.z,wv.w);
        #pragma unroll
        for (int r=0;r<4;r++) {
          float4 x = *(const float4*)&sX2[(q4*4+r)*260+f0];
          a2[r] = f2fma(pk2(x.x,x.y), w01, a2[r]);
          a2[r] = f2fma(pk2(x.z,x.w), w23, a2[r]);
        }
      }
      float bb = sb2[d64];
      #pragma unroll
      for (int r=0;r<4;r++){
        float2 p = upk(a2[r]);
        sZ2[(q4*4+r)*68+d64] = p.x + p.y + bb;
      }
    }
    // ---- Attn1 coefficients c[i,j] = tok[i]*lrv[j]*(xq_i.xk_j + 1), j<=i
    {
      float c = 0.0f;
      if (l16 <= i16) {
        u64t acc = 0ULL;
        #pragma unroll
        for (int d0=0; d0<64; d0+=4) {
          float4 xq = *(const float4*)&sXQ[i16*68+d0];
          float4 xk = *(const float4*)&sXK[l16*68+d0];
          acc = f2fma(pk2(xq.x,xq.y), pk2(xk.x,xk.y), acc);
          acc = f2fma(pk2(xq.z,xq.w), pk2(xk.z,xk.w), acc);
        }
        float2 p = upk(acc);
        c = sTok[i16]*sLr[l16]*(p.x + p.y + 1.0f);
      }
      sC[i16*17+l16] = c;
    }
    __syncthreads();

    // ---- gZ2 = ln_fused_l2_bwd(Z2, XV-XK)
    {
      int base = i16*68 + l16*4;
      float4 x = *(const float4*)&sZ2[base];
      float s  = x.x+x.y+x.z+x.w;
      float ss = x.x*x.x + x.y*x.y + x.z*x.z + x.w*x.w;
      #pragma unroll
      for (int o=8;o;o>>=1){ s += __shfl_xor_sync(0xffffffffu, s, o); ss += __shfl_xor_sync(0xffffffffu, ss, o); }
      float mu = s*(1.0f/64.0f);
      float var = ss*(1.0f/64.0f) - mu*mu;
      float rstd = rsqrtf(var + 1e-6f);
      float4 xh;
      xh.x=(x.x-mu)*rstd; xh.y=(x.y-mu)*rstd; xh.z=(x.z-mu)*rstd; xh.w=(x.w-mu)*rstd;
      float4 g  = *(const float4*)&sLW[l16*4];
      float4 bb = *(const float4*)&sLB[l16*4];
      float4 xv = *(const float4*)&sXV[base];
      float4 xk = *(const float4*)&sXK[base];
      float4 go;
      go.x = (g.x*xh.x + bb.x - (xv.x - xk.x))*g.x;
      go.y = (g.y*xh.y + bb.y - (xv.y - xk.y))*g.y;
      go.z = (g.z*xh.z + bb.z - (xv.z - xk.z))*g.z;
      go.w = (g.w*xh.w + bb.w - (xv.w - xk.w))*g.w;
      float sg  = go.x+go.y+go.z+go.w;
      float sgx = go.x*xh.x + go.y*xh.y + go.z*xh.z + go.w*xh.w;
      #pragma unroll
      for (int o=8;o;o>>=1){ sg += __shfl_xor_sync(0xffffffffu, sg, o); sgx += __shfl_xor_sync(0xffffffffu, sgx, o); }
      float k1 = rstd*(1.0f/64.0f);
      float4 o4;
      o4.x = (64.0f*go.x - sg - xh.x*sgx)*k1;
      o4.y = (64.0f*go.y - sg - xh.y*sgx)*k1;
      o4.z = (64.0f*go.z - sg - xh.z*sgx)*k1;
      o4.w = (64.0f*go.w - sg - xh.w*sgx)*k1;
      *(float4*)&sG2[base] = o4;
    }
    __syncthreads();

    // ---- gZ1 = (gZ2 @ W2^T) * gelu_bwd(Z1)  (thread: cols fp2,fp2+1 ; rows rh*8..+8)
    {
      u64t acc[8];
      #pragma unroll
      for (int i=0;i<8;i++) acc[i]=0ULL;
      #pragma unroll 4
      for (int d0=0; d0<64; d0+=2) {
        u64t w0 = *(const u64t*)&sW2T[(d0+0)*260 + fp2];
        u64t w1 = *(const u64t*)&sW2T[(d0+1)*260 + fp2];
        #pragma unroll
        for (int i8=0;i8<8;i8++) {
          float2 g2 = *(const float2*)&sG2[(rh*8+i8)*68 + d0];
          acc[i8] = f2fma(pk2(g2.x,g2.x), w0, acc[i8]);
          acc[i8] = f2fma(pk2(g2.y,g2.y), w1, acc[i8]);
        }
      }
      #pragma unroll
      for (int i8=0;i8<8;i8++){
        int i = rh*8+i8;
        float2 p = upk(acc[i8]);
        sG1[i*260+fp2]   = p.x * gelu_bwd_f(sZ1[i*260+fp2]);
        sG1[i*260+fp2+1] = p.y * gelu_bwd_f(sZ1[i*260+fp2+1]);
      }
    }
    __syncthreads();

    // ---- Z1_bar -> X2_bar = gelu(Z1_bar)  (column t, overwrite sZ1)
    {
      u64t acc[16];
      #pragma unroll
      for (int i=0;i<16;i++) acc[i]=0ULL;
      const float* wp = &sW1T[t*68];
      #pragma unroll 4
      for (int d0=0; d0<64; d0+=4) {
        float4 wv = *(const float4*)&wp[d0];
        u64t w01 = pk2(wv.x,wv.y), w23 = pk2(wv.z,wv.w);
        #pragma unroll
        for (int i=0;i<16;i++) {
          float4 xq = *(const float4*)&sXQ[i*68+d0];
          acc[i] = f2fma(pk2(xq.x,xq.y), w01, acc[i]);
          acc[i] = f2fma(pk2(xq.z,xq.w), w23, acc[i]);
        }
      }
      float gz[16];
      #pragma unroll
      for (int j=0;j<16;j++) gz[j] = sG1[j*260+t];
      float bb = sb1[t];
      #pragma unroll
      for (int i=0;i<16;i++){
        float2 p = upk(acc[i]);
        float a = p.x + p.y + bb;
        #pragma unroll
        for (int j=0;j<=i;j++) a -= sC[i*17+j]*gz[j];
        sZ1[i*260+t] = gelu_f(a);
      }
    }
    __syncthreads();

    // ---- Attn2 coefficients c2[i,j] = tok[i]*lrv[j]*(x2bar_i . x2_j + 1), j<=i
    {
      float c = 0.0f;
      if (l16 <= i16) {
        u64t acc = 0ULL;
        #pragma unroll 8
        for (int f0=0; f0<256; f0+=4) {
          float4 xb = *(const float4*)&sZ1[i16*260+f0];
          float4 x2 = *(const float4*)&sX2[l16*260+f0];
          acc = f2fma(pk2(xb.x,xb.y), pk2(x2.x,x2.y), acc);
          acc = f2fma(pk2(xb.z,xb.w), pk2(x2.z,x2.w), acc);
        }
        float2 p = upk(acc);
        c = sTok[i16]*sLr[l16]*(p.x + p.y + 1.0f);
      }
      sC[i16*17+l16] = c;
    }
    __syncthreads();

    // ---- Z2_bar = X2bar@W2 + b2 - corrections  (col d64, rows q4*4..+4) -> sZ2
    {
      u64t a2[4];
      #pragma unroll
      for (int r=0;r<4;r++) a2[r]=0ULL;
      const float* wp = &sW2T[d64*260];
      #pragma unroll 4
      for (int f0=0; f0<256; f0+=4) {
        float4 wv = *(const float4*)&wp[f0];
        u64t w01 = pk2(wv.x,wv.y), w23 = pk2(wv.z,wv.w);
        #pragma unroll
        for (int r=0;r<4;r++) {
          float4 x = *(const float4*)&sZ1[(q4*4+r)*260+f0];
          a2[r] = f2fma(pk2(x.x,x.y), w01, a2[r]);
          a2[r] = f2fma(pk2(x.z,x.w), w23, a2[r]);
        }
      }
      float gz[16];
      #pragma unroll
      for (int j=0;j<16;j++) gz[j] = sG2[j*68+d64];
      float bb = sb2[d64];
      #pragma unroll
      for (int r=0;r<4;r++){
        int i = q4*4+r;
        float2 p = upk(a2[r]);
        float a = p.x + p.y + bb;
        for (int j=0;j<=i;j++) a -= sC[i*17+j]*gz[j];
        sZ2[i*68+d64] = a;
      }
    }
    __syncthreads();

    // ---- output: Y = XQ + ln_fwd(Z2_bar)
    {
      int base = i16*68 + l16*4;
      float4 x = *(const float4*)&sZ2[base];
      float s  = x.x+x.y+x.z+x.w;
      float ss = x.x*x.x + x.y*x.y + x.z*x.z + x.w*x.w;
      #pragma unroll
      for (int o=8;o;o>>=1){ s += __shfl_xor_sync(0xffffffffu, s, o); ss += __shfl_xor_sync(0xffffffffu, ss, o); }
      float mu = s*(1.0f/64.0f);
      float var = ss*(1.0f/64.0f) - mu*mu;
      float rstd = rsqrtf(var + 1e-6f);
      float4 g  = *(const float4*)&sLW[l16*4];
      float4 bb = *(const float4*)&sLB[l16*4];
      float4 xq = *(const float4*)&sXQ[base];
      float4 o4;
      o4.x = g.x*(x.x-mu)*rstd + bb.x + xq.x;
      o4.y = g.y*(x.y-mu)*rstd + bb.y + xq.y;
      o4.z = g.z*(x.z-mu)*rstd + bb.z + xq.z;
      o4.w = g.w*(x.w-mu)*rstd + bb.w + xq.w;
      size_t gbase = ((size_t)(b*CL + l0 + i16))*CC + h*CHD + l16*4;
      *(float4*)&Y[gbase] = o4;
    }

    // ---- W1/b1 update (thread t owns W1T row t: contiguous in d)
    {
      float le15 = sTok[15];
      u64t cg2[16]; float bsum = 0.f;
      #pragma unroll
      for (int j=0;j<16;j++){
        float cgj = le15*sLr[j]*sG1[j*260+t];
        bsum += cgj;
        cg2[j] = pk2(cgj, cgj);
      }
      sb1[t] -= bsum;
      float* wp = &sW1T[t*68];
      #pragma unroll 2
      for (int d0=0; d0<64; d0+=4){
        u64t s01=0ULL, s23=0ULL;
        #pragma unroll
        for (int j=0;j<16;j++){
          float4 xk = *(const float4*)&sXK[j*68+d0];
          s01 = f2fma(pk2(xk.x,xk.y), cg2[j], s01);
          s23 = f2fma(pk2(xk.z,xk.w), cg2[j], s23);
        }
        float4 wv = *(const float4*)&wp[d0];
        float2 p01 = upk(s01), p23 = upk(s23);
        wv.x -= p01.x; wv.y -= p01.y; wv.z -= p23.x; wv.w -= p23.y;
        *(float4*)&wp[d0] = wv;
      }
    }
    // ---- W2/b2 update (thread (d64,q4) owns W2T[d64][q4*64..+64])
    {
      float le15 = sTok[15];
      u64t cg2[16]; float bsum = 0.f;
      #pragma unroll
      for (int j=0;j<16;j++){
        float cgj = le15*sLr[j]*sG2[j*68+d64];
        bsum += cgj;
        cg2[j] = pk2(cgj, cgj);
      }
      if (q4 == 0) sb2[d64] -= bsum;
      float* wp = &sW2T[d64*260 + q4*64];
      #pragma unroll 2
      for (int m=0; m<16; m++){
        int f0 = m*4;
        u64t s01=0ULL, s23=0ULL;
        #pragma unroll
        for (int j=0;j<16;j++){
          float4 x2 = *(const float4*)&sX2[j*260 + q4*64 + f0];
          s01 = f2fma(pk2(x2.x,x2.y), cg2[j], s01);
          s23 = f2fma(pk2(x2.z,x2.w), cg2[j], s23);
        }
        float4 wv = *(const float4*)&wp[f0];
        float2 p01 = upk(s01), p23 = upk(s23);
        wv.x -= p01.x; wv.y -= p01.y; wv.z -= p23.x; wv.w -= p23.y;
        *(float4*)&wp[f0] = wv;
      }
    }
    __syncthreads();
  }
}

// ---------------- post layernorm over C=1024 --------------------------------
__global__ __launch_bounds__(256) void postln_kernel(
    const float* __restrict__ X, const float* __restrict__ g,
    const float* __restrict__ b, float* __restrict__ O)
{
  __shared__ float rs[8], rss[8], stats[2];
  int row = blockIdx.x, t = threadIdx.x;
  float4 x = ((const float4*)(X + (size_t)row*CC))[t];
  float s  = x.x+x.y+x.z+x.w;
  float ss = x.x*x.x + x.y*x.y + x.z*x.z + x.w*x.w;
  #pragma unroll
  for (int o=16;o;o>>=1){ s += __shfl_xor_sync(0xffffffffu, s, o); ss += __shfl_xor_sync(0xffffffffu, ss, o); }
  if ((t & 31) == 0){ rs[t>>5] = s; rss[t>>5] = ss; }
  __syncthreads();
  if (t == 0){
    float a=0.f, c=0.f;
    #pragma unroll
    for (int w=0;w<8;w++){ a += rs[w]; c += rss[w]; }
    stats[0] = a*(1.0f/1024.0f);
    stats[1] = c*(1.0f/1024.0f);
  }
  __syncthreads();
  float mu = stats[0];
  float var = stats[1] - mu*mu;
  float rstd = rsqrtf(var + 1e-6f);
  float4 gv = ((const float4*)g)[t];
  float4 bv = ((const float4*)b)[t];
  float4 o4;
  o4.x = gv.x*(x.x-mu)*rstd + bv.x;
  o4.y = gv.y*(x.y-mu)*rstd + bv.y;
  o4.z = gv.z*(x.z-mu)*rstd + bv.z;
  o4.w = gv.w*(x.w-mu)*rstd + bv.w;
  ((float4*)(O + (size_t)row*CC))[t] = o4;
}

// ---------------- launch -----------------------------------------------------
extern "C" void kernel_launch(void* const* d_in, const int* in_sizes, int n_in,
                              void* d_out, int out_size)
{
  const float* hs  = (const float*)d_in[0];
  const float* wq  = (const float*)d_in[1];
  const float* wk  = (const float*)d_in[2];
  const float* wv  = (const float*)d_in[3];
  const float* wo  = (const float*)d_in[4];
  const float* lti = (const float*)d_in[5];
  const float* lrw = (const float*)d_in[6];
  const float* lrb = (const float*)d_in[7];
  const float* tnw = (const float*)d_in[8];
  const float* tnb = (const float*)d_in[9];
  const float* pnw = (const float*)d_in[10];
  const float* pnb = (const float*)d_in[11];
  const float* W1  = (const float*)d_in[12];
  const float* b1  = (const float*)d_in[13];
  const float* W2  = (const float*)d_in[14];
  const float* b2  = (const float*)d_in[15];
  float* out = (float*)d_out;

  float *pQ, *pK, *pV, *pY, *pLR;
  cudaGetSymbolAddress((void**)&pQ,  g_Q);
  cudaGetSymbolAddress((void**)&pK,  g_K);
  cudaGetSymbolAddress((void**)&pV,  g_V);
  cudaGetSymbolAddress((void**)&pY,  g_Y);
  cudaGetSymbolAddress((void**)&pLR, g_LR);

  cudaFuncSetAttribute(scan_kernel, cudaFuncAttributeMaxDynamicSharedMemorySize, SCAN_SMEM);

  const int M = CB*CL;  // 8192
  const int GG = (M/128)*(CC/128);  // 512
  gemm_tf32<<<GG, 256>>>(hs, wq, pQ, M, CC, CC);
  gemm_tf32<<<GG, 256>>>(hs, wk, pK, M, CC, CC);
  gemm_tf32<<<GG, 256>>>(hs, wv, pV, M, CC, CC);
  rope_kernel<<<(2*CB*CL*CNH*(CHD/2))/256, 256>>>(pQ, pK);
  lr_kernel<<<CB*CL, 256>>>(hs, lrw, lrb, pLR);
  scan_kernel<<<CB*CNH, 256, SCAN_SMEM>>>(pQ, pK, pV, pLR, lti, tnw, tnb,
                                          W1, b1, W2, b2, pY);
  postln_kernel<<<CB*CL, 256>>>(pY, pnw, pnb, pQ);
  gemm_tf32<<<GG, 256>>>(pQ, wo, out, M, CC, CC);
}